// round 2
// baseline (speedup 1.0000x reference)
#include <cuda_runtime.h>

// Fused NeRF positional-encoding + 27x32 MLP + 32x1 head, fp32.
// 2 points per thread, all math packed via Blackwell f32x2 FMA (PTX-only).
// R1 change: weights for hidden units (j, j+1) stored adjacent as duplicated
// pairs so ONE LDS.128 (ulonglong2) feeds TWO packed FMAs — halves the LDS
// instruction count that bound the previous version (L1 pipe was 85.8%).

typedef unsigned long long u64;

#define TPB 256
#define NIN 27
#define HID 32
#define HID2 (HID / 2)

__device__ __forceinline__ u64 pack2(float a, float b) {
    u64 r; asm("mov.b64 %0, {%1,%2};" : "=l"(r) : "f"(a), "f"(b)); return r;
}
__device__ __forceinline__ void unpack2(u64 v, float& a, float& b) {
    asm("mov.b64 {%0,%1}, %2;" : "=f"(a), "=f"(b) : "l"(v));
}
__device__ __forceinline__ u64 fma2(u64 a, u64 b, u64 c) {
    u64 d; asm("fma.rn.f32x2 %0, %1, %2, %3;" : "=l"(d) : "l"(a), "l"(b), "l"(c)); return d;
}
__device__ __forceinline__ u64 mul2(u64 a, u64 b) {
    u64 d; asm("mul.rn.f32x2 %0, %1, %2;" : "=l"(d) : "l"(a), "l"(b)); return d;
}
#define K2(v) pack2((v), (v))

// Packed sincos of two independent args: Cody-Waite pi/2 reduction + minimax
// polys, branch-free quadrant fixup. FMA-pipe only, fast-math-immune.
__device__ __forceinline__ void sincos2(float a0, float a1, u64& s_out, u64& c_out) {
    const float TWO_OVER_PI = 0.63661977236758134308f;
    float j0 = rintf(a0 * TWO_OVER_PI);
    float j1 = rintf(a1 * TWO_OVER_PI);
    int i0 = (int)j0, i1 = (int)j1;
    u64 j2 = pack2(j0, j1);
    u64 r2 = fma2(j2, K2(-1.5707962513e+00f), pack2(a0, a1));
    r2 = fma2(j2, K2(-7.5497894159e-08f), r2);
    r2 = fma2(j2, K2(-5.3903029534e-15f), r2);
    u64 z = mul2(r2, r2);
    u64 p = fma2(z, K2(-1.9515295891e-04f), K2(8.3321608736e-03f));
    p = fma2(p, z, K2(-1.6666654611e-01f));
    u64 rz = mul2(r2, z);
    u64 s = fma2(p, rz, r2);
    u64 q = fma2(z, K2(2.4433157442e-05f), K2(-1.3887316255e-03f));
    q = fma2(q, z, K2(4.1666645683e-02f));
    q = fma2(q, z, K2(-0.5f));
    u64 c = fma2(q, z, K2(1.0f));

    float s0, s1, c0, c1;
    unpack2(s, s0, s1); unpack2(c, c0, c1);
    float ss0 = (i0 & 1) ? c0 : s0;
    float cs0 = (i0 & 1) ? s0 : c0;
    float ss1 = (i1 & 1) ? c1 : s1;
    float cs1 = (i1 & 1) ? s1 : c1;
    unsigned sg0 = (unsigned)(i0 & 2) << 30, cg0 = (unsigned)((i0 + 1) & 2) << 30;
    unsigned sg1 = (unsigned)(i1 & 2) << 30, cg1 = (unsigned)((i1 + 1) & 2) << 30;
    ss0 = __int_as_float(__float_as_int(ss0) ^ sg0);
    cs0 = __int_as_float(__float_as_int(cs0) ^ cg0);
    ss1 = __int_as_float(__float_as_int(ss1) ^ sg1);
    cs1 = __int_as_float(__float_as_int(cs1) ^ cg1);
    s_out = pack2(ss0, ss1);
    c_out = pack2(cs0, cs1);
}

__global__ void __launch_bounds__(TPB) nerf_fused_kernel(
    const float* __restrict__ x,
    const float* __restrict__ W1,
    const float* __restrict__ b1,
    const float* __restrict__ W2,
    const float* __restrict__ b2,
    float* __restrict__ out, int N)
{
    // sW1v[i][j2] = { dup(W1[i][2*j2]), dup(W1[i][2*j2+1]) }  -> one LDS.128
    __shared__ __align__(16) ulonglong2 sW1v[NIN * HID2];   // 6912 B
    __shared__ __align__(16) ulonglong2 sB1v[HID2];
    __shared__ __align__(16) ulonglong2 sW2v[HID2];
    __shared__ float sB2;

    for (int k = threadIdx.x; k < NIN * HID; k += TPB) {
        int i = k / HID, j = k % HID;
        float w = W1[k];
        u64 d = pack2(w, w);
        if (j & 1) sW1v[i * HID2 + (j >> 1)].y = d;
        else       sW1v[i * HID2 + (j >> 1)].x = d;
    }
    if (threadIdx.x < HID) {
        int j = threadIdx.x;
        float v = b1[j];
        float w = W2[j];
        if (j & 1) { sB1v[j >> 1].y = pack2(v, v); sW2v[j >> 1].y = pack2(w, w); }
        else       { sB1v[j >> 1].x = pack2(v, v); sW2v[j >> 1].x = pack2(w, w); }
    }
    if (threadIdx.x == 0) sB2 = b2[0];
    __syncthreads();

    int t = blockIdx.x * TPB + threadIdx.x;
    long long p = 2LL * t;
    if (p >= N) return;
    bool full = (p + 1 < N);

    float x0, y0, z0, x1, y1, z1;
    if (full) {
        const float2* xv = (const float2*)x;
        float2 a = xv[3 * t];
        float2 bq = xv[3 * t + 1];
        float2 cq = xv[3 * t + 2];
        x0 = a.x; y0 = a.y; z0 = bq.x; x1 = bq.y; y1 = cq.x; z1 = cq.y;
    } else {
        x0 = x[p * 3]; y0 = x[p * 3 + 1]; z0 = x[p * 3 + 2];
        x1 = x0; y1 = y0; z1 = z0;
    }

    const float f1 = exp2f(3.3333333333333335f);
    const float f2 = exp2f(6.666666666666667f);

    u64 tf[NIN];
    tf[0] = pack2(x0, x1);
    tf[1] = pack2(y0, y1);
    tf[2] = pack2(z0, z1);
    {
        float fv;
        fv = 1.0f;
        sincos2(x0 * fv, x1 * fv, tf[3 + 0], tf[3 + 3]);
        sincos2(y0 * fv, y1 * fv, tf[3 + 1], tf[3 + 4]);
        sincos2(z0 * fv, z1 * fv, tf[3 + 2], tf[3 + 5]);
        fv = f1;
        sincos2(x0 * fv, x1 * fv, tf[9 + 0], tf[9 + 3]);
        sincos2(y0 * fv, y1 * fv, tf[9 + 1], tf[9 + 4]);
        sincos2(z0 * fv, z1 * fv, tf[9 + 2], tf[9 + 5]);
        fv = f2;
        sincos2(x0 * fv, x1 * fv, tf[15 + 0], tf[15 + 3]);
        sincos2(y0 * fv, y1 * fv, tf[15 + 1], tf[15 + 4]);
        sincos2(z0 * fv, z1 * fv, tf[15 + 2], tf[15 + 5]);
        fv = 1024.0f;
        sincos2(x0 * fv, x1 * fv, tf[21 + 0], tf[21 + 3]);
        sincos2(y0 * fv, y1 * fv, tf[21 + 1], tf[21 + 4]);
        sincos2(z0 * fv, z1 * fv, tf[21 + 2], tf[21 + 5]);
    }

    // MLP: two hidden units per j2 step; one LDS.128 feeds two FFMA2.
    u64 acc = K2(0.0f);
    #pragma unroll
    for (int j2 = 0; j2 < HID2; j2++) {
        ulonglong2 bv = sB1v[j2];
        u64 h0 = bv.x, h1 = bv.y;
        #pragma unroll
        for (int i = 0; i < NIN; i++) {
            ulonglong2 w = sW1v[i * HID2 + j2];
            h0 = fma2(tf[i], w.x, h0);
            h1 = fma2(tf[i], w.y, h1);
        }
        float a0, a1, c0, c1;
        unpack2(h0, a0, a1); unpack2(h1, c0, c1);
        a0 = fmaxf(a0, 0.0f); a1 = fmaxf(a1, 0.0f);
        c0 = fmaxf(c0, 0.0f); c1 = fmaxf(c1, 0.0f);
        ulonglong2 w2 = sW2v[j2];
        acc = fma2(pack2(a0, a1), w2.x, acc);
        acc = fma2(pack2(c0, c1), w2.y, acc);
    }

    float o0, o1; unpack2(acc, o0, o1);
    float bb = sB2;
    o0 = fmaxf(o0 + bb, 0.0f);
    o1 = fmaxf(o1 + bb, 0.0f);
    if (full) {
        ((float2*)out)[t] = make_float2(o0, o1);
    } else {
        out[p] = o0;
    }
}

extern "C" void kernel_launch(void* const* d_in, const int* in_sizes, int n_in,
                              void* d_out, int out_size) {
    const float* x  = (const float*)d_in[0];
    const float* W1 = (const float*)d_in[1];
    const float* b1 = (const float*)d_in[2];
    const float* W2 = (const float*)d_in[3];
    const float* b2 = (const float*)d_in[4];
    float* out = (float*)d_out;

    int N = in_sizes[0] / 3;
    int pairs = (N + 1) / 2;
    int blocks = (pairs + TPB - 1) / TPB;
    nerf_fused_kernel<<<blocks, TPB>>>(x, W1, b1, W2, b2, out, N);
}

// round 3
// speedup vs baseline: 1.2146x; 1.2146x over previous
#include <cuda_runtime.h>

// Fused NeRF positional-encoding + 27x32 MLP + 32x1 head, fp32.
// R2: 4 points per thread (two f32x2 pairs A,B). Each broadcast LDS.64 of a
// duplicated weight now feeds TWO packed FMAs (4 MACs), halving per-point
// smem wavefronts (the R0/R1 binding resource). FMA pipe becomes the cap.

typedef unsigned long long u64;

#define TPB 128
#define NIN 27
#define HID 32

__device__ __forceinline__ u64 pack2(float a, float b) {
    u64 r; asm("mov.b64 %0, {%1,%2};" : "=l"(r) : "f"(a), "f"(b)); return r;
}
__device__ __forceinline__ void unpack2(u64 v, float& a, float& b) {
    asm("mov.b64 {%0,%1}, %2;" : "=f"(a), "=f"(b) : "l"(v));
}
__device__ __forceinline__ u64 fma2(u64 a, u64 b, u64 c) {
    u64 d; asm("fma.rn.f32x2 %0, %1, %2, %3;" : "=l"(d) : "l"(a), "l"(b), "l"(c)); return d;
}
__device__ __forceinline__ u64 mul2(u64 a, u64 b) {
    u64 d; asm("mul.rn.f32x2 %0, %1, %2;" : "=l"(d) : "l"(a), "l"(b)); return d;
}
#define K2(v) pack2((v), (v))

// Packed sincos: Cody-Waite pi/2 reduction + minimax polys, branch-free
// quadrant fixup. FMA-pipe only, fast-math-immune, ~1e-7 for |arg|<1e4.
__device__ __forceinline__ void sincos2(float a0, float a1, u64& s_out, u64& c_out) {
    const float TWO_OVER_PI = 0.63661977236758134308f;
    float j0 = rintf(a0 * TWO_OVER_PI);
    float j1 = rintf(a1 * TWO_OVER_PI);
    int i0 = (int)j0, i1 = (int)j1;
    u64 j2 = pack2(j0, j1);
    u64 r2 = fma2(j2, K2(-1.5707962513e+00f), pack2(a0, a1));
    r2 = fma2(j2, K2(-7.5497894159e-08f), r2);
    r2 = fma2(j2, K2(-5.3903029534e-15f), r2);
    u64 z = mul2(r2, r2);
    u64 p = fma2(z, K2(-1.9515295891e-04f), K2(8.3321608736e-03f));
    p = fma2(p, z, K2(-1.6666654611e-01f));
    u64 rz = mul2(r2, z);
    u64 s = fma2(p, rz, r2);
    u64 q = fma2(z, K2(2.4433157442e-05f), K2(-1.3887316255e-03f));
    q = fma2(q, z, K2(4.1666645683e-02f));
    q = fma2(q, z, K2(-0.5f));
    u64 c = fma2(q, z, K2(1.0f));

    float s0, s1, c0, c1;
    unpack2(s, s0, s1); unpack2(c, c0, c1);
    float ss0 = (i0 & 1) ? c0 : s0;
    float cs0 = (i0 & 1) ? s0 : c0;
    float ss1 = (i1 & 1) ? c1 : s1;
    float cs1 = (i1 & 1) ? s1 : c1;
    unsigned sg0 = (unsigned)(i0 & 2) << 30, cg0 = (unsigned)((i0 + 1) & 2) << 30;
    unsigned sg1 = (unsigned)(i1 & 2) << 30, cg1 = (unsigned)((i1 + 1) & 2) << 30;
    ss0 = __int_as_float(__float_as_int(ss0) ^ sg0);
    cs0 = __int_as_float(__float_as_int(cs0) ^ cg0);
    ss1 = __int_as_float(__float_as_int(ss1) ^ sg1);
    cs1 = __int_as_float(__float_as_int(cs1) ^ cg1);
    s_out = pack2(ss0, ss1);
    c_out = pack2(cs0, cs1);
}

// Build the 27 packed features for a point pair (x0..z1) into tf[].
__device__ __forceinline__ void encode_pair(
    float x0, float y0, float z0, float x1, float y1, float z1, u64* tf)
{
    const float f1 = exp2f(3.3333333333333335f);
    const float f2 = exp2f(6.666666666666667f);
    tf[0] = pack2(x0, x1);
    tf[1] = pack2(y0, y1);
    tf[2] = pack2(z0, z1);
    float fv;
    fv = 1.0f;
    sincos2(x0 * fv, x1 * fv, tf[3 + 0], tf[3 + 3]);
    sincos2(y0 * fv, y1 * fv, tf[3 + 1], tf[3 + 4]);
    sincos2(z0 * fv, z1 * fv, tf[3 + 2], tf[3 + 5]);
    fv = f1;
    sincos2(x0 * fv, x1 * fv, tf[9 + 0], tf[9 + 3]);
    sincos2(y0 * fv, y1 * fv, tf[9 + 1], tf[9 + 4]);
    sincos2(z0 * fv, z1 * fv, tf[9 + 2], tf[9 + 5]);
    fv = f2;
    sincos2(x0 * fv, x1 * fv, tf[15 + 0], tf[15 + 3]);
    sincos2(y0 * fv, y1 * fv, tf[15 + 1], tf[15 + 4]);
    sincos2(z0 * fv, z1 * fv, tf[15 + 2], tf[15 + 5]);
    fv = 1024.0f;
    sincos2(x0 * fv, x1 * fv, tf[21 + 0], tf[21 + 3]);
    sincos2(y0 * fv, y1 * fv, tf[21 + 1], tf[21 + 4]);
    sincos2(z0 * fv, z1 * fv, tf[21 + 2], tf[21 + 5]);
}

__global__ void __launch_bounds__(TPB, 1) nerf_fused_kernel(
    const float* __restrict__ x,
    const float* __restrict__ W1,
    const float* __restrict__ b1,
    const float* __restrict__ W2,
    const float* __restrict__ b2,
    float* __restrict__ out, int N)
{
    __shared__ u64 sW1[NIN * HID];   // duplicated (w,w) pairs
    __shared__ u64 sB1[HID];
    __shared__ u64 sW2[HID];
    __shared__ float sB2;

    for (int k = threadIdx.x; k < NIN * HID; k += TPB) {
        float w = W1[k];
        sW1[k] = pack2(w, w);
    }
    if (threadIdx.x < HID) {
        float v = b1[threadIdx.x]; sB1[threadIdx.x] = pack2(v, v);
        float w = W2[threadIdx.x]; sW2[threadIdx.x] = pack2(w, w);
    }
    if (threadIdx.x == 0) sB2 = b2[0];
    __syncthreads();

    long long t = (long long)blockIdx.x * TPB + threadIdx.x;
    long long p = 4LL * t;               // first of 4 points
    if (p >= N) return;
    bool full = (p + 3 < N);

    float c0x, c0y, c0z, c1x, c1y, c1z, c2x, c2y, c2z, c3x, c3y, c3z;
    if (full) {
        const float4* xv = (const float4*)x;    // 4 points = 12 floats = 3 float4
        float4 a = xv[3 * t];
        float4 bq = xv[3 * t + 1];
        float4 cq = xv[3 * t + 2];
        c0x = a.x;  c0y = a.y;  c0z = a.z;
        c1x = a.w;  c1y = bq.x; c1z = bq.y;
        c2x = bq.z; c2y = bq.w; c2z = cq.x;
        c3x = cq.y; c3y = cq.z; c3z = cq.w;
    } else {
        long long m = N - 1;
        long long p0 = p, p1 = p + 1 > m ? m : p + 1, p2 = p + 2 > m ? m : p + 2, p3 = p + 3 > m ? m : p + 3;
        c0x = x[p0*3]; c0y = x[p0*3+1]; c0z = x[p0*3+2];
        c1x = x[p1*3]; c1y = x[p1*3+1]; c1z = x[p1*3+2];
        c2x = x[p2*3]; c2y = x[p2*3+1]; c2z = x[p2*3+2];
        c3x = x[p3*3]; c3y = x[p3*3+1]; c3z = x[p3*3+2];
    }

    u64 tfA[NIN], tfB[NIN];
    encode_pair(c0x, c0y, c0z, c1x, c1y, c1z, tfA);
    encode_pair(c2x, c2y, c2z, c3x, c3y, c3z, tfB);

    // MLP: one broadcast LDS.64 weight feeds 2 packed FMAs (4 MACs).
    u64 accA = K2(0.0f), accB = K2(0.0f);
    #pragma unroll 4
    for (int j = 0; j < HID; j++) {
        u64 bj = sB1[j];
        u64 hA = bj, hB = bj;
        #pragma unroll
        for (int i = 0; i < NIN; i++) {
            u64 w = sW1[i * HID + j];
            hA = fma2(tfA[i], w, hA);
            hB = fma2(tfB[i], w, hB);
        }
        float a0, a1, b0v, b1v;
        unpack2(hA, a0, a1); unpack2(hB, b0v, b1v);
        a0 = fmaxf(a0, 0.0f); a1 = fmaxf(a1, 0.0f);
        b0v = fmaxf(b0v, 0.0f); b1v = fmaxf(b1v, 0.0f);
        u64 w2 = sW2[j];
        accA = fma2(pack2(a0, a1), w2, accA);
        accB = fma2(pack2(b0v, b1v), w2, accB);
    }

    float o0, o1, o2, o3;
    unpack2(accA, o0, o1); unpack2(accB, o2, o3);
    float bb = sB2;
    o0 = fmaxf(o0 + bb, 0.0f);
    o1 = fmaxf(o1 + bb, 0.0f);
    o2 = fmaxf(o2 + bb, 0.0f);
    o3 = fmaxf(o3 + bb, 0.0f);
    if (full) {
        ((float4*)out)[t] = make_float4(o0, o1, o2, o3);
    } else {
        long long m = N;
        if (p     < m) out[p]     = o0;
        if (p + 1 < m) out[p + 1] = o1;
        if (p + 2 < m) out[p + 2] = o2;
        if (p + 3 < m) out[p + 3] = o3;
    }
}

extern "C" void kernel_launch(void* const* d_in, const int* in_sizes, int n_in,
                              void* d_out, int out_size) {
    const float* x  = (const float*)d_in[0];
    const float* W1 = (const float*)d_in[1];
    const float* b1 = (const float*)d_in[2];
    const float* W2 = (const float*)d_in[3];
    const float* b2 = (const float*)d_in[4];
    float* out = (float*)d_out;

    int N = in_sizes[0] / 3;
    long long quads = (N + 3) / 4;
    int blocks = (int)((quads + TPB - 1) / TPB);
    nerf_fused_kernel<<<blocks, TPB>>>(x, W1, b1, W2, b2, out, N);
}